// round 1
// baseline (speedup 1.0000x reference)
#include <cuda_runtime.h>
#include <cuda_bf16.h>
#include <math.h>

// Problem constants
#define EMB   1024
#define NHEAD 16
#define HDIM  64
#define LQ    2048
#define BB    2
#define SS    2048
#define MROWS (LQ * BB)   // 4096 rows for all projections

// ---------------- device scratch (no allocation allowed) ----------------
__device__ float g_q[MROWS * EMB];
__device__ float g_k[MROWS * EMB];
__device__ float g_v[MROWS * EMB];
__device__ float g_ctx[MROWS * EMB];

// ---------------------------------------------------------------------------
// SGEMM: C[M,N] = A[M,K] @ W[N,K]^T + bias[N]
// BM=BN=128, BK=16, 256 threads, 8x8 microtile. M%128==0, N%128==0, K%16==0.
// ---------------------------------------------------------------------------
__global__ __launch_bounds__(256)
void sgemm_bias(const float* __restrict__ A, const float* __restrict__ W,
                const float* __restrict__ bias, float* __restrict__ C,
                int M, int N, int K)
{
    const int BM = 128, BN = 128, BK = 16, LDS_PAD = 132;
    __shared__ float As[BK][LDS_PAD];
    __shared__ float Bs[BK][LDS_PAD];

    const int tid = threadIdx.x;
    const int tm = tid >> 4;      // 0..15
    const int tn = tid & 15;      // 0..15
    const int m0 = blockIdx.y * BM;
    const int n0 = blockIdx.x * BN;

    float acc[8][8];
#pragma unroll
    for (int i = 0; i < 8; ++i)
#pragma unroll
        for (int j = 0; j < 8; ++j) acc[i][j] = 0.0f;

    const int ktiles = K / BK;
    for (int kt = 0; kt < ktiles; ++kt) {
        const int k0 = kt * BK;
        // load A tile (128 x 16) and W tile (128 x 16), stored K-major transposed
#pragma unroll
        for (int p = 0; p < 2; ++p) {
            int idx = tid + p * 256;
            int row = idx >> 2;
            int c4  = (idx & 3) * 4;
            float4 av = *reinterpret_cast<const float4*>(
                A + (size_t)(m0 + row) * K + k0 + c4);
            As[c4 + 0][row] = av.x; As[c4 + 1][row] = av.y;
            As[c4 + 2][row] = av.z; As[c4 + 3][row] = av.w;
            float4 bv = *reinterpret_cast<const float4*>(
                W + (size_t)(n0 + row) * K + k0 + c4);
            Bs[c4 + 0][row] = bv.x; Bs[c4 + 1][row] = bv.y;
            Bs[c4 + 2][row] = bv.z; Bs[c4 + 3][row] = bv.w;
        }
        __syncthreads();

#pragma unroll
        for (int kk = 0; kk < BK; ++kk) {
            float4 a0 = *reinterpret_cast<const float4*>(&As[kk][tm * 8]);
            float4 a1 = *reinterpret_cast<const float4*>(&As[kk][tm * 8 + 4]);
            float4 b0 = *reinterpret_cast<const float4*>(&Bs[kk][tn * 8]);
            float4 b1 = *reinterpret_cast<const float4*>(&Bs[kk][tn * 8 + 4]);
            float a[8] = {a0.x, a0.y, a0.z, a0.w, a1.x, a1.y, a1.z, a1.w};
            float b[8] = {b0.x, b0.y, b0.z, b0.w, b1.x, b1.y, b1.z, b1.w};
#pragma unroll
            for (int i = 0; i < 8; ++i)
#pragma unroll
                for (int j = 0; j < 8; ++j)
                    acc[i][j] = fmaf(a[i], b[j], acc[i][j]);
        }
        __syncthreads();
    }

    // epilogue with bias
#pragma unroll
    for (int i = 0; i < 8; ++i) {
        size_t row = (size_t)(m0 + tm * 8 + i) * N + n0 + tn * 8;
#pragma unroll
        for (int j4 = 0; j4 < 2; ++j4) {
            int j = j4 * 4;
            float4 o;
            o.x = acc[i][j + 0] + bias[n0 + tn * 8 + j + 0];
            o.y = acc[i][j + 1] + bias[n0 + tn * 8 + j + 1];
            o.z = acc[i][j + 2] + bias[n0 + tn * 8 + j + 2];
            o.w = acc[i][j + 3] + bias[n0 + tn * 8 + j + 3];
            *reinterpret_cast<float4*>(C + row + j) = o;
        }
    }
}

// ---------------------------------------------------------------------------
// Flash attention: per (b,h), 64-query blocks, 64-key tiles, online softmax.
// q/k/v layout: [(t*B + b)*EMB + h*64 + d]  (projection output layout).
// 1/sqrt(64) = 0.125 folded into Q load.
// smem: Qt[64][68] (d-major), Kt[64][68] (d-major, reused as Pt[s][68]),
//       Vs[64][64] (s-major).
// ---------------------------------------------------------------------------
#define FLASH_SMEM_FLOATS (2 * 64 * 68 + 64 * 64)

__global__ __launch_bounds__(256)
void flash_attn(const float* __restrict__ gq, const float* __restrict__ gk,
                const float* __restrict__ gv, float* __restrict__ ctx)
{
    extern __shared__ float sm[];
    float* Qt = sm;                 // [64][68]
    float* Kt = sm + 64 * 68;       // [64][68]  (also Pt)
    float* Vs = sm + 2 * 64 * 68;   // [64][64]

    const int tid = threadIdx.x;
    const int ty = tid >> 4;   // 0..15 -> query rows ty*4..+3
    const int tx = tid & 15;   // 0..15 -> key cols / d cols tx*4..+3

    const int q0 = blockIdx.x * 64;
    const int bh = blockIdx.y;
    const int b  = bh & (BB - 1);
    const int h  = bh >> 1;
    const size_t hoff = (size_t)h * HDIM;

    // load Q tile, scaled, transposed to d-major
    for (int idx = tid; idx < 64 * 16; idx += 256) {
        int i  = idx >> 4;
        int d4 = (idx & 15) * 4;
        float4 v = *reinterpret_cast<const float4*>(
            gq + ((size_t)(q0 + i) * BB + b) * EMB + hoff + d4);
        Qt[(d4 + 0) * 68 + i] = v.x * 0.125f;
        Qt[(d4 + 1) * 68 + i] = v.y * 0.125f;
        Qt[(d4 + 2) * 68 + i] = v.z * 0.125f;
        Qt[(d4 + 3) * 68 + i] = v.w * 0.125f;
    }

    float m_i[4], l_i[4], Oacc[4][4];
#pragma unroll
    for (int i = 0; i < 4; ++i) {
        m_i[i] = -1e30f; l_i[i] = 0.0f;
#pragma unroll
        for (int j = 0; j < 4; ++j) Oacc[i][j] = 0.0f;
    }

    for (int s0 = 0; s0 < SS; s0 += 64) {
        __syncthreads();  // protect Kt/Pt/Vs from previous iteration readers
        // load K (d-major transposed) and V (s-major)
        for (int idx = tid; idx < 64 * 16; idx += 256) {
            int j  = idx >> 4;
            int d4 = (idx & 15) * 4;
            size_t base = ((size_t)(s0 + j) * BB + b) * EMB + hoff + d4;
            float4 kv = *reinterpret_cast<const float4*>(gk + base);
            Kt[(d4 + 0) * 68 + j] = kv.x;
            Kt[(d4 + 1) * 68 + j] = kv.y;
            Kt[(d4 + 2) * 68 + j] = kv.z;
            Kt[(d4 + 3) * 68 + j] = kv.w;
            float4 vv = *reinterpret_cast<const float4*>(gv + base);
            *reinterpret_cast<float4*>(&Vs[j * 64 + d4]) = vv;
        }
        __syncthreads();

        // scores S = (Q*scale) @ K^T : 64x64, 4x4 per thread
        float sc[4][4];
#pragma unroll
        for (int i = 0; i < 4; ++i)
#pragma unroll
            for (int j = 0; j < 4; ++j) sc[i][j] = 0.0f;

#pragma unroll 16
        for (int kk = 0; kk < 64; ++kk) {
            float4 qa = *reinterpret_cast<const float4*>(&Qt[kk * 68 + ty * 4]);
            float4 kb = *reinterpret_cast<const float4*>(&Kt[kk * 68 + tx * 4]);
            float a[4] = {qa.x, qa.y, qa.z, qa.w};
            float c[4] = {kb.x, kb.y, kb.z, kb.w};
#pragma unroll
            for (int i = 0; i < 4; ++i)
#pragma unroll
                for (int j = 0; j < 4; ++j)
                    sc[i][j] = fmaf(a[i], c[j], sc[i][j]);
        }

        // online softmax (row groups of 16 lanes share same ty)
        float p[4][4];
#pragma unroll
        for (int i = 0; i < 4; ++i) {
            float t = fmaxf(fmaxf(sc[i][0], sc[i][1]), fmaxf(sc[i][2], sc[i][3]));
#pragma unroll
            for (int off = 8; off >= 1; off >>= 1)
                t = fmaxf(t, __shfl_xor_sync(0xffffffffu, t, off));
            float mnew = fmaxf(m_i[i], t);
            float corr = __expf(m_i[i] - mnew);
            float rsum = 0.0f;
#pragma unroll
            for (int j = 0; j < 4; ++j) {
                p[i][j] = __expf(sc[i][j] - mnew);
                rsum += p[i][j];
            }
#pragma unroll
            for (int off = 8; off >= 1; off >>= 1)
                rsum += __shfl_xor_sync(0xffffffffu, rsum, off);
            l_i[i] = l_i[i] * corr + rsum;
            m_i[i] = mnew;
#pragma unroll
            for (int j = 0; j < 4; ++j) Oacc[i][j] *= corr;
        }
        __syncthreads();  // everyone done reading Kt

        // stage P into Kt buffer as Pt[s][i] (s-major rows of 68)
#pragma unroll
        for (int j = 0; j < 4; ++j)
#pragma unroll
            for (int i = 0; i < 4; ++i)
                Kt[(tx * 4 + j) * 68 + ty * 4 + i] = p[i][j];
        __syncthreads();

        // O += P @ V
#pragma unroll 16
        for (int kk = 0; kk < 64; ++kk) {
            float4 pv = *reinterpret_cast<const float4*>(&Kt[kk * 68 + ty * 4]);
            float4 vv = *reinterpret_cast<const float4*>(&Vs[kk * 64 + tx * 4]);
            float a[4] = {pv.x, pv.y, pv.z, pv.w};
            float c[4] = {vv.x, vv.y, vv.z, vv.w};
#pragma unroll
            for (int i = 0; i < 4; ++i)
#pragma unroll
                for (int j = 0; j < 4; ++j)
                    Oacc[i][j] = fmaf(a[i], c[j], Oacc[i][j]);
        }
    }

    // normalize + store context in (L,B,E) projection layout
#pragma unroll
    for (int i = 0; i < 4; ++i) {
        float inv = 1.0f / l_i[i];
        float4 o;
        o.x = Oacc[i][0] * inv; o.y = Oacc[i][1] * inv;
        o.z = Oacc[i][2] * inv; o.w = Oacc[i][3] * inv;
        *reinterpret_cast<float4*>(
            ctx + ((size_t)(q0 + ty * 4 + i) * BB + b) * EMB + hoff + tx * 4) = o;
    }
}

// ---------------------------------------------------------------------------
extern "C" void kernel_launch(void* const* d_in, const int* in_sizes, int n_in,
                              void* d_out, int out_size)
{
    const float* query = (const float*)d_in[0];
    const float* key   = (const float*)d_in[1];
    const float* value = (const float*)d_in[2];
    const float* w_in  = (const float*)d_in[3];
    const float* b_in  = (const float*)d_in[4];
    const float* w_out = (const float*)d_in[5];
    const float* b_out = (const float*)d_in[6];
    float* out = (float*)d_out;

    float *q, *k, *v, *ctx;
    cudaGetSymbolAddress((void**)&q,   g_q);
    cudaGetSymbolAddress((void**)&k,   g_k);
    cudaGetSymbolAddress((void**)&v,   g_v);
    cudaGetSymbolAddress((void**)&ctx, g_ctx);

    dim3 gemm_grid(EMB / 128, MROWS / 128);  // (8, 32)
    sgemm_bias<<<gemm_grid, 256>>>(query, w_in,               b_in,           q, MROWS, EMB, EMB);
    sgemm_bias<<<gemm_grid, 256>>>(key,   w_in + EMB * EMB,   b_in + EMB,     k, MROWS, EMB, EMB);
    sgemm_bias<<<gemm_grid, 256>>>(value, w_in + 2 * EMB * EMB, b_in + 2 * EMB, v, MROWS, EMB, EMB);

    int smem = FLASH_SMEM_FLOATS * sizeof(float);  // 51200 bytes
    cudaFuncSetAttribute(flash_attn, cudaFuncAttributeMaxDynamicSharedMemorySize, smem);
    dim3 flash_grid(LQ / 64, BB * NHEAD);  // (32, 32)
    flash_attn<<<flash_grid, 256, smem>>>(q, k, v, ctx);

    sgemm_bias<<<gemm_grid, 256>>>(ctx, w_out, b_out, out, MROWS, EMB, EMB);
}

// round 6
// speedup vs baseline: 2.5271x; 2.5271x over previous
#include <cuda_runtime.h>
#include <cuda_bf16.h>
#include <math.h>
#include <cstdint>

// Problem constants
#define EMB   1024
#define NHEAD 16
#define HDIM  64
#define LQ    2048
#define BB    2
#define SS    2048
#define MROWS (LQ * BB)   // 4096
#define KDIM  1024

// ---------------- device scratch (no allocation allowed) ----------------
__device__ float g_q[MROWS * EMB];
__device__ float g_k[MROWS * EMB];
__device__ float g_v[MROWS * EMB];
__device__ float g_ctx[MROWS * EMB];

// ======================= helpers =======================
__device__ __forceinline__ uint32_t f2tf32(float x) {
    uint32_t u;
    asm("cvt.rna.tf32.f32 %0, %1;" : "=r"(u) : "f"(x));
    return u;
}

// d += a @ b  (m16n8k8 tf32, row.col)
__device__ __forceinline__ void mma8(float* d, uint32_t a0, uint32_t a1,
                                     uint32_t a2, uint32_t a3,
                                     uint32_t b0, uint32_t b1) {
    asm volatile(
        "mma.sync.aligned.m16n8k8.row.col.f32.tf32.tf32.f32 "
        "{%0,%1,%2,%3}, {%4,%5,%6,%7}, {%8,%9}, {%0,%1,%2,%3};"
        : "+f"(d[0]), "+f"(d[1]), "+f"(d[2]), "+f"(d[3])
        : "r"(a0), "r"(a1), "r"(a2), "r"(a3), "r"(b0), "r"(b1));
}

// ===========================================================================
// tf32 mma.sync GEMM: C[4096,1024] = A[4096,1024] @ W[1024,1024]^T + bias
// BM=BN=128, BK=32, double-buffered smem (pitch 36), 8 warps, 64x32 per warp.
// blockIdx.z selects (A, W-chunk, bias-chunk, C) for fused QKV projection.
// ===========================================================================
#define GP 36   // smem pitch (floats): 36 % 32 == 4 -> conflict-free frags

__global__ __launch_bounds__(256)
void gemm_mma(const float* __restrict__ A0, const float* __restrict__ A1,
              const float* __restrict__ A2, const float* __restrict__ W,
              const float* __restrict__ bias,
              float* __restrict__ C0, float* __restrict__ C1,
              float* __restrict__ C2)
{
    extern __shared__ uint32_t sm[];
    uint32_t* As = sm;                   // [2][128][GP]
    uint32_t* Ws = sm + 2 * 128 * GP;    // [2][128][GP]

    const int z = blockIdx.z;
    const float* A = (z == 0) ? A0 : (z == 1) ? A1 : A2;
    const float* Wz = W + (size_t)z * EMB * EMB;
    const float* bz = bias + z * EMB;
    float* C = (z == 0) ? C0 : (z == 1) ? C1 : C2;

    const int tid = threadIdx.x;
    const int warp = tid >> 5;
    const int lane = tid & 31;
    const int gid = lane >> 2;
    const int tig = lane & 3;
    const int wm = warp & 3;     // m-block of 32 rows
    const int wn = warp >> 2;    // n-block of 64 cols
    const int m0 = blockIdx.y * 128;
    const int n0 = blockIdx.x * 128;

    float acc[2][8][4];
#pragma unroll
    for (int mt = 0; mt < 2; ++mt)
#pragma unroll
        for (int nt = 0; nt < 8; ++nt)
#pragma unroll
            for (int r = 0; r < 4; ++r) acc[mt][nt][r] = 0.0f;

    // gmem load mapping: idx = p*256+tid -> row = idx>>3, c4 = (idx&7)*4
#pragma unroll
    for (int p = 0; p < 4; ++p) {
        int idx = p * 256 + tid;
        int row = idx >> 3;
        int c = (idx & 7) * 4;
        float4 va = *reinterpret_cast<const float4*>(A + (size_t)(m0 + row) * KDIM + c);
        float4 vw = *reinterpret_cast<const float4*>(Wz + (size_t)(n0 + row) * KDIM + c);
        uint32_t* da = As + row * GP + c;
        da[0] = f2tf32(va.x); da[1] = f2tf32(va.y); da[2] = f2tf32(va.z); da[3] = f2tf32(va.w);
        uint32_t* dw = Ws + row * GP + c;
        dw[0] = f2tf32(vw.x); dw[1] = f2tf32(vw.y); dw[2] = f2tf32(vw.z); dw[3] = f2tf32(vw.w);
    }
    __syncthreads();

    for (int kt = 0; kt < 32; ++kt) {
        const int s = kt & 1;
        float4 bA[4], bW[4];
        if (kt < 31) {
            const int kb = (kt + 1) * 32;
#pragma unroll
            for (int p = 0; p < 4; ++p) {
                int idx = p * 256 + tid;
                int row = idx >> 3;
                int c = (idx & 7) * 4;
                bA[p] = *reinterpret_cast<const float4*>(A + (size_t)(m0 + row) * KDIM + kb + c);
                bW[p] = *reinterpret_cast<const float4*>(Wz + (size_t)(n0 + row) * KDIM + kb + c);
            }
        }

        const uint32_t* Ac = As + s * 128 * GP;
        const uint32_t* Wc = Ws + s * 128 * GP;
#pragma unroll
        for (int ks = 0; ks < 4; ++ks) {
            uint32_t a[2][4];
#pragma unroll
            for (int mt = 0; mt < 2; ++mt) {
                const uint32_t* p = Ac + (wm * 32 + mt * 16 + gid) * GP + ks * 8 + tig;
                a[mt][0] = p[0]; a[mt][2] = p[4];
                a[mt][1] = p[8 * GP]; a[mt][3] = p[8 * GP + 4];
            }
#pragma unroll
            for (int nt = 0; nt < 8; ++nt) {
                const uint32_t* q = Wc + (wn * 64 + nt * 8 + gid) * GP + ks * 8 + tig;
                uint32_t b0 = q[0], b1 = q[4];
                mma8(acc[0][nt], a[0][0], a[0][1], a[0][2], a[0][3], b0, b1);
                mma8(acc[1][nt], a[1][0], a[1][1], a[1][2], a[1][3], b0, b1);
            }
        }

        if (kt < 31) {
            uint32_t* da = As + (s ^ 1) * 128 * GP;
            uint32_t* dw = Ws + (s ^ 1) * 128 * GP;
#pragma unroll
            for (int p = 0; p < 4; ++p) {
                int idx = p * 256 + tid;
                int row = idx >> 3;
                int c = (idx & 7) * 4;
                uint32_t* ta = da + row * GP + c;
                ta[0] = f2tf32(bA[p].x); ta[1] = f2tf32(bA[p].y);
                ta[2] = f2tf32(bA[p].z); ta[3] = f2tf32(bA[p].w);
                uint32_t* tw = dw + row * GP + c;
                tw[0] = f2tf32(bW[p].x); tw[1] = f2tf32(bW[p].y);
                tw[2] = f2tf32(bW[p].z); tw[3] = f2tf32(bW[p].w);
            }
            __syncthreads();
        }
    }

    // epilogue: direct STG with bias
#pragma unroll
    for (int mt = 0; mt < 2; ++mt) {
        int r = m0 + wm * 32 + mt * 16 + gid;
#pragma unroll
        for (int nt = 0; nt < 8; ++nt) {
            int c = n0 + wn * 64 + nt * 8 + 2 * tig;
            float bx = bz[c], by = bz[c + 1];
            float2 o0 = make_float2(acc[mt][nt][0] + bx, acc[mt][nt][1] + by);
            float2 o1 = make_float2(acc[mt][nt][2] + bx, acc[mt][nt][3] + by);
            *reinterpret_cast<float2*>(C + (size_t)r * EMB + c) = o0;
            *reinterpret_cast<float2*>(C + (size_t)(r + 8) * EMB + c) = o1;
        }
    }
}

// ===========================================================================
// Flash attention with tf32 mma.sync.
// CTA: 128 queries x 128 keys, 8 warps; warp owns 16 query rows.
// smem (u32/tf32): Qs[128][68], Ks[128][68], Vs[128][68], Ps[8][16][132].
// ===========================================================================
#define FP 68    // q/k/v pitch (68 % 32 == 4)
#define PP 132   // P pitch (132 % 32 == 4)
#define SM_Q 0
#define SM_K (128 * FP)
#define SM_V (2 * 128 * FP)
#define SM_P (3 * 128 * FP)
#define F_SMEM_U32 (3 * 128 * FP + 8 * 16 * PP)   // 43008 u32 = 172032 B

__global__ __launch_bounds__(256)
void flash_attn(const float* __restrict__ gq, const float* __restrict__ gk,
                const float* __restrict__ gv, float* __restrict__ ctx)
{
    extern __shared__ uint32_t sm[];
    uint32_t* Qs = sm + SM_Q;
    uint32_t* Ks = sm + SM_K;
    uint32_t* Vs = sm + SM_V;
    uint32_t* Pw = sm + SM_P + (threadIdx.x >> 5) * 16 * PP;  // warp-private

    const int tid = threadIdx.x;
    const int warp = tid >> 5;
    const int lane = tid & 31;
    const int gid = lane >> 2;
    const int tig = lane & 3;

    const int q0 = blockIdx.x * 128;
    const int bh = blockIdx.y;
    const int b = bh & (BB - 1);
    const int h = bh >> 1;
    const size_t hoff = (size_t)h * HDIM;

    // load Q (128 x 64), scale 1/8, tf32, row-major pitch FP
    for (int idx = tid; idx < 128 * 16; idx += 256) {
        int i = idx >> 4;
        int d4 = (idx & 15) * 4;
        float4 v = *reinterpret_cast<const float4*>(
            gq + ((size_t)(q0 + i) * BB + b) * EMB + hoff + d4);
        uint32_t* dq = Qs + i * FP + d4;
        dq[0] = f2tf32(v.x * 0.125f); dq[1] = f2tf32(v.y * 0.125f);
        dq[2] = f2tf32(v.z * 0.125f); dq[3] = f2tf32(v.w * 0.125f);
    }

    float m0r = -1e30f, m1r = -1e30f, l0 = 0.0f, l1 = 0.0f;
    float Of[8][4];
#pragma unroll
    for (int nt = 0; nt < 8; ++nt)
#pragma unroll
        for (int r = 0; r < 4; ++r) Of[nt][r] = 0.0f;

    const int rowQ = warp * 16;

    for (int s0 = 0; s0 < SS; s0 += 128) {
        __syncthreads();  // prev-iter Vs/Ks readers done
        for (int idx = tid; idx < 128 * 16; idx += 256) {
            int j = idx >> 4;
            int d4 = (idx & 15) * 4;
            size_t base = ((size_t)(s0 + j) * BB + b) * EMB + hoff + d4;
            float4 kv = *reinterpret_cast<const float4*>(gk + base);
            uint32_t* dk = Ks + j * FP + d4;
            dk[0] = f2tf32(kv.x); dk[1] = f2tf32(kv.y);
            dk[2] = f2tf32(kv.z); dk[3] = f2tf32(kv.w);
            float4 vv = *reinterpret_cast<const float4*>(gv + base);
            uint32_t* dv = Vs + j * FP + d4;
            dv[0] = f2tf32(vv.x); dv[1] = f2tf32(vv.y);
            dv[2] = f2tf32(vv.z); dv[3] = f2tf32(vv.w);
        }
        __syncthreads();

        // S = Q @ K^T : warp computes 16 x 128 (16 n-tiles), k = 64 (8 steps)
        float sfr[16][4];
#pragma unroll
        for (int nt = 0; nt < 16; ++nt)
#pragma unroll
            for (int r = 0; r < 4; ++r) sfr[nt][r] = 0.0f;

#pragma unroll
        for (int ks = 0; ks < 8; ++ks) {
            const uint32_t* qa = Qs + (rowQ + gid) * FP + ks * 8 + tig;
            uint32_t a0 = qa[0], a2 = qa[4];
            uint32_t a1 = qa[8 * FP], a3 = qa[8 * FP + 4];
#pragma unroll
            for (int nt = 0; nt < 16; ++nt) {
                const uint32_t* kb = Ks + (nt * 8 + gid) * FP + ks * 8 + tig;
                mma8(sfr[nt], a0, a1, a2, a3, kb[0], kb[4]);
            }
        }

        // online softmax: thread owns rows gid (c0,c1) and gid+8 (c2,c3)
        float mx0 = sfr[0][0], mx1 = sfr[0][2];
#pragma unroll
        for (int nt = 0; nt < 16; ++nt) {
            mx0 = fmaxf(mx0, fmaxf(sfr[nt][0], sfr[nt][1]));
            mx1 = fmaxf(mx1, fmaxf(sfr[nt][2], sfr[nt][3]));
        }
#pragma unroll
        for (int off = 1; off <= 2; off <<= 1) {
            mx0 = fmaxf(mx0, __shfl_xor_sync(0xffffffffu, mx0, off));
            mx1 = fmaxf(mx1, __shfl_xor_sync(0xffffffffu, mx1, off));
        }
        float mn0 = fmaxf(m0r, mx0), mn1 = fmaxf(m1r, mx1);
        float c0 = __expf(m0r - mn0), c1 = __expf(m1r - mn1);
        float s0a = 0.0f, s1a = 0.0f;
#pragma unroll
        for (int nt = 0; nt < 16; ++nt) {
            sfr[nt][0] = __expf(sfr[nt][0] - mn0);
            sfr[nt][1] = __expf(sfr[nt][1] - mn0);
            sfr[nt][2] = __expf(sfr[nt][2] - mn1);
            sfr[nt][3] = __expf(sfr[nt][3] - mn1);
            s0a += sfr[nt][0] + sfr[nt][1];
            s1a += sfr[nt][2] + sfr[nt][3];
        }
#pragma unroll
        for (int off = 1; off <= 2; off <<= 1) {
            s0a += __shfl_xor_sync(0xffffffffu, s0a, off);
            s1a += __shfl_xor_sync(0xffffffffu, s1a, off);
        }
        l0 = l0 * c0 + s0a; l1 = l1 * c1 + s1a;
        m0r = mn0; m1r = mn1;
#pragma unroll
        for (int nt = 0; nt < 8; ++nt) {
            Of[nt][0] *= c0; Of[nt][1] *= c0;
            Of[nt][2] *= c1; Of[nt][3] *= c1;
        }

        // stage P (tf32) into warp-private smem [16][PP]
#pragma unroll
        for (int nt = 0; nt < 16; ++nt) {
            int c = nt * 8 + 2 * tig;
            Pw[gid * PP + c]       = f2tf32(sfr[nt][0]);
            Pw[gid * PP + c + 1]   = f2tf32(sfr[nt][1]);
            Pw[(gid + 8) * PP + c]     = f2tf32(sfr[nt][2]);
            Pw[(gid + 8) * PP + c + 1] = f2tf32(sfr[nt][3]);
        }
        __syncwarp();

        // O += P @ V : 8 n-tiles (d=64), k = 128 (16 steps)
#pragma unroll
        for (int ks = 0; ks < 16; ++ks) {
            const uint32_t* pa = Pw + gid * PP + ks * 8 + tig;
            uint32_t a0 = pa[0], a2 = pa[4];
            uint32_t a1 = pa[8 * PP], a3 = pa[8 * PP + 4];
#pragma unroll
            for (int nt = 0; nt < 8; ++nt) {
                const uint32_t* pv = Vs + (ks * 8 + tig) * FP + nt * 8 + gid;
                mma8(Of[nt], a0, a1, a2, a3, pv[0], pv[4 * FP]);
            }
        }
        __syncwarp();  // P reads done before next iteration rewrites
    }

    // normalize + store ctx
    float i0 = 1.0f / l0, i1 = 1.0f / l1;
    int r = q0 + rowQ + gid;
#pragma unroll
    for (int nt = 0; nt < 8; ++nt) {
        int d = nt * 8 + 2 * tig;
        float2 o0 = make_float2(Of[nt][0] * i0, Of[nt][1] * i0);
        float2 o1 = make_float2(Of[nt][2] * i1, Of[nt][3] * i1);
        *reinterpret_cast<float2*>(ctx + ((size_t)r * BB + b) * EMB + hoff + d) = o0;
        *reinterpret_cast<float2*>(ctx + ((size_t)(r + 8) * BB + b) * EMB + hoff + d) = o1;
    }
}

// ---------------------------------------------------------------------------
extern "C" void kernel_launch(void* const* d_in, const int* in_sizes, int n_in,
                              void* d_out, int out_size)
{
    const float* query = (const float*)d_in[0];
    const float* key   = (const float*)d_in[1];
    const float* value = (const float*)d_in[2];
    const float* w_in  = (const float*)d_in[3];
    const float* b_in  = (const float*)d_in[4];
    const float* w_out = (const float*)d_in[5];
    const float* b_out = (const float*)d_in[6];
    float* out = (float*)d_out;

    float *q, *k, *v, *ctx;
    cudaGetSymbolAddress((void**)&q,   g_q);
    cudaGetSymbolAddress((void**)&k,   g_k);
    cudaGetSymbolAddress((void**)&v,   g_v);
    cudaGetSymbolAddress((void**)&ctx, g_ctx);

    const int gemm_smem = 2 * 2 * 128 * GP * 4;  // 73728 B
    cudaFuncSetAttribute(gemm_mma, cudaFuncAttributeMaxDynamicSharedMemorySize, gemm_smem);

    // fused QKV projection: grid z = 3
    dim3 qkv_grid(EMB / 128, MROWS / 128, 3);
    gemm_mma<<<qkv_grid, 256, gemm_smem>>>(query, key, value, w_in, b_in, q, k, v);

    const int fl_smem = F_SMEM_U32 * 4;  // 172032 B
    cudaFuncSetAttribute(flash_attn, cudaFuncAttributeMaxDynamicSharedMemorySize, fl_smem);
    dim3 flash_grid(LQ / 128, BB * NHEAD);  // (16, 32)
    flash_attn<<<flash_grid, 256, fl_smem>>>(q, k, v, ctx);

    // out projection: single z
    dim3 out_grid(EMB / 128, MROWS / 128, 1);
    gemm_mma<<<out_grid, 256, gemm_smem>>>(ctx, ctx, ctx, w_out, b_out, out, out, out);
}

// round 9
// speedup vs baseline: 4.6297x; 1.8320x over previous
#include <cuda_runtime.h>
#include <cuda_fp16.h>
#include <math.h>
#include <cstdint>

// Problem constants
#define EMB   1024
#define NHEAD 16
#define HDIM  64
#define LQ    2048
#define BB    2
#define SS    2048
#define MROWS (LQ * BB)   // 4096
#define KDIM  1024

// ---------------- device scratch (no allocation allowed) ----------------
__device__ float g_q[MROWS * EMB];
__device__ float g_k[MROWS * EMB];
__device__ float g_v[MROWS * EMB];
__device__ float g_ctx[MROWS * EMB];

// ======================= helpers =======================
__device__ __forceinline__ uint32_t smem_u32(const void* p) {
    uint32_t a;
    asm("{ .reg .u64 t; cvta.to.shared.u64 t, %1; cvt.u32.u64 %0, t; }"
        : "=r"(a) : "l"(p));
    return a;
}

// pack two f32 into f16x2 (hi goes to upper half)
__device__ __forceinline__ uint32_t packh2(float hi, float lo) {
    uint32_t r;
    asm("cvt.rn.f16x2.f32 %0, %1, %2;" : "=r"(r) : "f"(hi), "f"(lo));
    return r;
}

__device__ __forceinline__ uint32_t h2ex2(uint32_t x) {
    uint32_t r;
    asm("ex2.approx.f16x2 %0, %1;" : "=r"(r) : "r"(x));
    return r;
}

__device__ __forceinline__ float ex2f(float x) {
    float y;
    asm("ex2.approx.ftz.f32 %0, %1;" : "=f"(y) : "f"(x));
    return y;
}

// d += a @ b  (m16n8k16 f16 in, f32 accum, row.col)
__device__ __forceinline__ void mma16(float* d, uint32_t a0, uint32_t a1,
                                      uint32_t a2, uint32_t a3,
                                      uint32_t b0, uint32_t b1) {
    asm volatile(
        "mma.sync.aligned.m16n8k16.row.col.f32.f16.f16.f32 "
        "{%0,%1,%2,%3}, {%4,%5,%6,%7}, {%8,%9}, {%0,%1,%2,%3};"
        : "+f"(d[0]), "+f"(d[1]), "+f"(d[2]), "+f"(d[3])
        : "r"(a0), "r"(a1), "r"(a2), "r"(a3), "r"(b0), "r"(b1));
}

__device__ __forceinline__ void ldsm4(uint32_t& r0, uint32_t& r1,
                                      uint32_t& r2, uint32_t& r3, uint32_t addr) {
    asm volatile("ldmatrix.sync.aligned.m8n8.x4.shared.b16 {%0,%1,%2,%3}, [%4];"
                 : "=r"(r0), "=r"(r1), "=r"(r2), "=r"(r3) : "r"(addr));
}

__device__ __forceinline__ void ldsm4t(uint32_t& r0, uint32_t& r1,
                                       uint32_t& r2, uint32_t& r3, uint32_t addr) {
    asm volatile("ldmatrix.sync.aligned.m8n8.x4.trans.shared.b16 {%0,%1,%2,%3}, [%4];"
                 : "=r"(r0), "=r"(r1), "=r"(r2), "=r"(r3) : "r"(addr));
}

// ===========================================================================
// fp16 mma GEMM: C[4096,1024] = A[4096,1024] @ W[1024,1024]^T + bias (f32 io)
// BM=BN=128, BK=32 halves, double-buffered, 8 warps (4m x 2n), warp 32m x 64n.
// ===========================================================================
#define GPH 40   // smem pitch in halves (80B rows: conflict-free for ldmatrix)

__global__ __launch_bounds__(256)
void gemm_h(const float* __restrict__ A0, const float* __restrict__ A1,
            const float* __restrict__ A2, const float* __restrict__ W,
            const float* __restrict__ bias,
            float* __restrict__ C0, float* __restrict__ C1,
            float* __restrict__ C2)
{
    extern __shared__ __half smh[];
    const uint32_t sb = smem_u32(smh);
    uint32_t* smu = reinterpret_cast<uint32_t*>(smh);
    // halves offsets: As[2][128][GPH], Ws[2][128][GPH]
    const uint32_t OFF_W = 2 * 128 * GPH;

    const int z = blockIdx.z;
    const float* A = (z == 0) ? A0 : (z == 1) ? A1 : A2;
    const float* Wz = W + (size_t)z * EMB * EMB;
    const float* bz = bias + z * EMB;
    float* C = (z == 0) ? C0 : (z == 1) ? C1 : C2;

    const int tid = threadIdx.x;
    const int warp = tid >> 5;
    const int lane = tid & 31;
    const int gid = lane >> 2;
    const int tig = lane & 3;
    const int ri = lane & 7;
    const int mi = lane >> 3;
    const int wm = warp & 3;
    const int wn = warp >> 2;
    const int m0 = blockIdx.y * 128;
    const int n0 = blockIdx.x * 128;

    float acc[2][8][4];
#pragma unroll
    for (int mt = 0; mt < 2; ++mt)
#pragma unroll
        for (int nt = 0; nt < 8; ++nt)
#pragma unroll
            for (int r = 0; r < 4; ++r) acc[mt][nt][r] = 0.0f;

    // load mapping: idx = p*256 + tid -> row = idx>>3, 4-f32 group c = (idx&7)*4
#pragma unroll
    for (int p = 0; p < 4; ++p) {
        int idx = p * 256 + tid;
        int row = idx >> 3;
        int c = (idx & 7) * 4;
        float4 va = *reinterpret_cast<const float4*>(A + (size_t)(m0 + row) * KDIM + c);
        float4 vw = *reinterpret_cast<const float4*>(Wz + (size_t)(n0 + row) * KDIM + c);
        smu[(row * GPH + c) >> 1]       = packh2(va.y, va.x);
        smu[((row * GPH + c) >> 1) + 1] = packh2(va.w, va.z);
        smu[(OFF_W + row * GPH + c) >> 1]       = packh2(vw.y, vw.x);
        smu[((OFF_W + row * GPH + c) >> 1) + 1] = packh2(vw.w, vw.z);
    }
    __syncthreads();

    for (int kt = 0; kt < 32; ++kt) {
        const int s = kt & 1;
        float4 bA[4], bW[4];
        if (kt < 31) {
            const int kb = (kt + 1) * 32;
#pragma unroll
            for (int p = 0; p < 4; ++p) {
                int idx = p * 256 + tid;
                int row = idx >> 3;
                int c = (idx & 7) * 4;
                bA[p] = *reinterpret_cast<const float4*>(A + (size_t)(m0 + row) * KDIM + kb + c);
                bW[p] = *reinterpret_cast<const float4*>(Wz + (size_t)(n0 + row) * KDIM + kb + c);
            }
        }

        const uint32_t baseA = sb + (uint32_t)(s * 128 * GPH) * 2;
        const uint32_t baseW = sb + (uint32_t)((OFF_W + s * 128 * GPH)) * 2;
#pragma unroll
        for (int ks = 0; ks < 2; ++ks) {
            const int k0 = ks * 16;
            uint32_t a[2][4];
#pragma unroll
            for (int mt = 0; mt < 2; ++mt) {
                uint32_t addr = baseA + 2 * ((wm * 32 + mt * 16 + ri + (mi & 1) * 8) * GPH
                                             + k0 + (mi >> 1) * 8);
                ldsm4(a[mt][0], a[mt][1], a[mt][2], a[mt][3], addr);
            }
#pragma unroll
            for (int nt2 = 0; nt2 < 4; ++nt2) {
                uint32_t b0, b1, b2, b3;
                uint32_t addr = baseW + 2 * ((wn * 64 + nt2 * 16 + ri + (mi >> 1) * 8) * GPH
                                             + k0 + (mi & 1) * 8);
                ldsm4(b0, b1, b2, b3, addr);
#pragma unroll
                for (int mt = 0; mt < 2; ++mt) {
                    mma16(acc[mt][2 * nt2],     a[mt][0], a[mt][1], a[mt][2], a[mt][3], b0, b1);
                    mma16(acc[mt][2 * nt2 + 1], a[mt][0], a[mt][1], a[mt][2], a[mt][3], b2, b3);
                }
            }
        }

        if (kt < 31) {
            const uint32_t d = (s ^ 1) * 128 * GPH;
#pragma unroll
            for (int p = 0; p < 4; ++p) {
                int idx = p * 256 + tid;
                int row = idx >> 3;
                int c = (idx & 7) * 4;
                smu[(d + row * GPH + c) >> 1]       = packh2(bA[p].y, bA[p].x);
                smu[((d + row * GPH + c) >> 1) + 1] = packh2(bA[p].w, bA[p].z);
                smu[(OFF_W + d + row * GPH + c) >> 1]       = packh2(bW[p].y, bW[p].x);
                smu[((OFF_W + d + row * GPH + c) >> 1) + 1] = packh2(bW[p].w, bW[p].z);
            }
            __syncthreads();
        }
    }

    // epilogue: direct STG with f32 bias
#pragma unroll
    for (int mt = 0; mt < 2; ++mt) {
        int r = m0 + wm * 32 + mt * 16 + gid;
#pragma unroll
        for (int nt = 0; nt < 8; ++nt) {
            int c = n0 + wn * 64 + nt * 8 + 2 * tig;
            float bx = bz[c], by = bz[c + 1];
            float2 o0 = make_float2(acc[mt][nt][0] + bx, acc[mt][nt][1] + by);
            float2 o1 = make_float2(acc[mt][nt][2] + bx, acc[mt][nt][3] + by);
            *reinterpret_cast<float2*>(C + (size_t)r * EMB + c) = o0;
            *reinterpret_cast<float2*>(C + (size_t)(r + 8) * EMB + c) = o1;
        }
    }
}

// ===========================================================================
// Flash attention, fp16 mma + base-2 softmax with ex2.approx.f16x2.
// CTA 128q x 128k, 8 warps; warp = 16 query rows. Row sums via ones-column mma.
// Q is pre-scaled by log2(e)/8; K is UNSCALED (fix for round-7 double-scale bug).
// smem halves: Q[128][72], K[128][72], V[128][72], P: 8 warps x [16][136].
// ===========================================================================
#define FPH 72
#define PPH 136
#define SQH 0
#define SKH (128 * FPH)
#define SVH (2 * 128 * FPH)
#define SPH (3 * 128 * FPH)
#define F_SMEM_BYTES ((3 * 128 * FPH + 8 * 16 * PPH) * 2)   // 90112

__global__ __launch_bounds__(256, 2)
void flash_attn(const float* __restrict__ gq, const float* __restrict__ gk,
                const float* __restrict__ gv, float* __restrict__ ctx)
{
    extern __shared__ __half smh[];
    const uint32_t sb = smem_u32(smh);
    uint32_t* smu = reinterpret_cast<uint32_t*>(smh);

    const int tid = threadIdx.x;
    const int warp = tid >> 5;
    const int lane = tid & 31;
    const int gid = lane >> 2;
    const int tig = lane & 3;
    const int ri = lane & 7;
    const int mi = lane >> 3;

    const int q0 = blockIdx.x * 128;
    const int bh = blockIdx.y;
    const int b = bh & (BB - 1);
    const int h = bh >> 1;
    const size_t hoff = (size_t)h * HDIM;
    const int rowQ = warp * 16;
    const uint32_t pwarp = SPH + warp * 16 * PPH;  // halves offset of warp P

    const float QSC = 0.180336880f;  // log2(e) / 8 — applied to Q ONLY

    // load Q (128 x 64), scale, f16
    for (int idx = tid; idx < 128 * 16; idx += 256) {
        int i = idx >> 4;
        int d = (idx & 15) * 4;
        float4 v = *reinterpret_cast<const float4*>(
            gq + ((size_t)(q0 + i) * BB + b) * EMB + hoff + d);
        smu[(SQH + i * FPH + d) >> 1]       = packh2(v.y * QSC, v.x * QSC);
        smu[((SQH + i * FPH + d) >> 1) + 1] = packh2(v.w * QSC, v.z * QSC);
    }

    float m0r = -1e30f, m1r = -1e30f, l0 = 0.0f, l1 = 0.0f;
    float Of[8][4];
#pragma unroll
    for (int nt = 0; nt < 8; ++nt)
#pragma unroll
        for (int r = 0; r < 4; ++r) Of[nt][r] = 0.0f;

    const uint32_t ones = (gid == 0) ? 0x3C003C00u : 0u;  // fp16 (1,1) at n==0

    for (int s0 = 0; s0 < SS; s0 += 128) {
        __syncthreads();  // prev-tile V readers done (also covers Q store once)
        for (int idx = tid; idx < 128 * 16; idx += 256) {
            int j = idx >> 4;
            int d = (idx & 15) * 4;
            size_t base = ((size_t)(s0 + j) * BB + b) * EMB + hoff + d;
            float4 kv = *reinterpret_cast<const float4*>(gk + base);
            smu[(SKH + j * FPH + d) >> 1]       = packh2(kv.y, kv.x);
            smu[((SKH + j * FPH + d) >> 1) + 1] = packh2(kv.w, kv.z);
            float4 vv = *reinterpret_cast<const float4*>(gv + base);
            smu[(SVH + j * FPH + d) >> 1]       = packh2(vv.y, vv.x);
            smu[((SVH + j * FPH + d) >> 1) + 1] = packh2(vv.w, vv.z);
        }
        __syncthreads();

        // ---- S = Q @ K^T in base-2 units: warp 16 x 128, k=64 (4 steps)
        float sfr[16][4];
#pragma unroll
        for (int nt = 0; nt < 16; ++nt)
#pragma unroll
            for (int r = 0; r < 4; ++r) sfr[nt][r] = 0.0f;

#pragma unroll
        for (int ks = 0; ks < 4; ++ks) {
            const int k0 = ks * 16;
            uint32_t a0, a1, a2, a3;
            ldsm4(a0, a1, a2, a3,
                  sb + 2 * (SQH + (rowQ + ri + (mi & 1) * 8) * FPH + k0 + (mi >> 1) * 8));
#pragma unroll
            for (int nt2 = 0; nt2 < 8; ++nt2) {
                uint32_t b0, b1, b2, b3;
                ldsm4(b0, b1, b2, b3,
                      sb + 2 * (SKH + (nt2 * 16 + ri + (mi >> 1) * 8) * FPH + k0 + (mi & 1) * 8));
                mma16(sfr[2 * nt2],     a0, a1, a2, a3, b0, b1);
                mma16(sfr[2 * nt2 + 1], a0, a1, a2, a3, b2, b3);
            }
        }

        // ---- online softmax (base 2). rows: gid (c0,c1), gid+8 (c2,c3)
        float mx0 = sfr[0][0], mx1 = sfr[0][2];
#pragma unroll
        for (int nt = 0; nt < 16; ++nt) {
            mx0 = fmaxf(mx0, fmaxf(sfr[nt][0], sfr[nt][1]));
            mx1 = fmaxf(mx1, fmaxf(sfr[nt][2], sfr[nt][3]));
        }
#pragma unroll
        for (int off = 1; off <= 2; off <<= 1) {
            mx0 = fmaxf(mx0, __shfl_xor_sync(0xffffffffu, mx0, off));
            mx1 = fmaxf(mx1, __shfl_xor_sync(0xffffffffu, mx1, off));
        }
        float mn0 = fmaxf(m0r, mx0), mn1 = fmaxf(m1r, mx1);
        float c0 = ex2f(m0r - mn0), c1 = ex2f(m1r - mn1);
        m0r = mn0; m1r = mn1;

        // P = 2^(s - mn) in fp16 pairs, staged to warp-private smem
#pragma unroll
        for (int nt = 0; nt < 16; ++nt) {
            uint32_t p0 = h2ex2(packh2(sfr[nt][1] - mn0, sfr[nt][0] - mn0));
            uint32_t p1 = h2ex2(packh2(sfr[nt][3] - mn1, sfr[nt][2] - mn1));
            smu[(pwarp + gid * PPH + nt * 8 + 2 * tig) >> 1] = p0;
            smu[(pwarp + (gid + 8) * PPH + nt * 8 + 2 * tig) >> 1] = p1;
        }
#pragma unroll
        for (int nt = 0; nt < 8; ++nt) {
            Of[nt][0] *= c0; Of[nt][1] *= c0;
            Of[nt][2] *= c1; Of[nt][3] *= c1;
        }
        float lacc[4] = {0.0f, 0.0f, 0.0f, 0.0f};
        __syncwarp();

        // ---- O += P @ V (and row-sum via ones column): k = 128 (8 steps)
#pragma unroll
        for (int ks = 0; ks < 8; ++ks) {
            const int k0 = ks * 16;
            uint32_t a0, a1, a2, a3;
            ldsm4(a0, a1, a2, a3,
                  sb + 2 * (pwarp + (ri + (mi & 1) * 8) * PPH + k0 + (mi >> 1) * 8));
#pragma unroll
            for (int dt2 = 0; dt2 < 4; ++dt2) {
                uint32_t b0, b1, b2, b3;
                ldsm4t(b0, b1, b2, b3,
                       sb + 2 * (SVH + (k0 + ri + (mi & 1) * 8) * FPH + dt2 * 16 + (mi >> 1) * 8));
                mma16(Of[2 * dt2],     a0, a1, a2, a3, b0, b1);
                mma16(Of[2 * dt2 + 1], a0, a1, a2, a3, b2, b3);
            }
            mma16(lacc, a0, a1, a2, a3, ones, ones);
        }
        l0 = l0 * c0 + lacc[0];
        l1 = l1 * c1 + lacc[2];
        __syncwarp();
    }

    // broadcast row sums from tig==0 lanes, normalize, store
    const int src = lane & ~3;
    float l0b = __shfl_sync(0xffffffffu, l0, src);
    float l1b = __shfl_sync(0xffffffffu, l1, src);
    float i0 = 1.0f / l0b, i1 = 1.0f / l1b;
    int r = q0 + rowQ + gid;
#pragma unroll
    for (int nt = 0; nt < 8; ++nt) {
        int d = nt * 8 + 2 * tig;
        float2 o0 = make_float2(Of[nt][0] * i0, Of[nt][1] * i0);
        float2 o1 = make_float2(Of[nt][2] * i1, Of[nt][3] * i1);
        *reinterpret_cast<float2*>(ctx + ((size_t)r * BB + b) * EMB + hoff + d) = o0;
        *reinterpret_cast<float2*>(ctx + ((size_t)(r + 8) * BB + b) * EMB + hoff + d) = o1;
    }
}

// ---------------------------------------------------------------------------
extern "C" void kernel_launch(void* const* d_in, const int* in_sizes, int n_in,
                              void* d_out, int out_size)
{
    const float* query = (const float*)d_in[0];
    const float* key   = (const float*)d_in[1];
    const float* value = (const float*)d_in[2];
    const float* w_in  = (const float*)d_in[3];
    const float* b_in  = (const float*)d_in[4];
    const float* w_out = (const float*)d_in[5];
    const float* b_out = (const float*)d_in[6];
    float* out = (float*)d_out;

    float *q, *k, *v, *ctx;
    cudaGetSymbolAddress((void**)&q,   g_q);
    cudaGetSymbolAddress((void**)&k,   g_k);
    cudaGetSymbolAddress((void**)&v,   g_v);
    cudaGetSymbolAddress((void**)&ctx, g_ctx);

    const int gemm_smem = 4 * 128 * GPH * 2;  // 40960 B
    cudaFuncSetAttribute(gemm_h, cudaFuncAttributeMaxDynamicSharedMemorySize, gemm_smem);

    dim3 qkv_grid(EMB / 128, MROWS / 128, 3);
    gemm_h<<<qkv_grid, 256, gemm_smem>>>(query, key, value, w_in, b_in, q, k, v);

    cudaFuncSetAttribute(flash_attn, cudaFuncAttributeMaxDynamicSharedMemorySize, F_SMEM_BYTES);
    dim3 flash_grid(LQ / 128, BB * NHEAD);  // (16, 32)
    flash_attn<<<flash_grid, 256, F_SMEM_BYTES>>>(q, k, v, ctx);

    dim3 out_grid(EMB / 128, MROWS / 128, 1);
    gemm_h<<<out_grid, 256, gemm_smem>>>(ctx, ctx, ctx, w_out, b_out, out, out, out);
}

// round 10
// speedup vs baseline: 6.6866x; 1.4443x over previous
#include <cuda_runtime.h>
#include <cuda_fp16.h>
#include <math.h>
#include <cstdint>

// Problem constants
#define EMB   1024
#define NHEAD 16
#define HDIM  64
#define LQ    2048
#define BB    2
#define SS    2048
#define MROWS (LQ * BB)   // 4096
#define KDIM  1024

// ---------------- device scratch (no allocation allowed) ----------------
__device__ __half g_ah[3 * MROWS * KDIM];   // converted query/key/value inputs
__device__ __half g_wh[4 * EMB * EMB];      // converted w_in (3M) + w_out (1M)
__device__ __half g_qh[MROWS * EMB];        // q projection (pre-scaled by log2e/8)
__device__ __half g_kh[MROWS * EMB];
__device__ __half g_vh[MROWS * EMB];
__device__ __half g_ch[MROWS * EMB];        // attention context (f16)

// ======================= helpers =======================
__device__ __forceinline__ uint32_t smem_u32(const void* p) {
    uint32_t a;
    asm("{ .reg .u64 t; cvta.to.shared.u64 t, %1; cvt.u32.u64 %0, t; }"
        : "=r"(a) : "l"(p));
    return a;
}

__device__ __forceinline__ uint32_t packh2(float hi, float lo) {
    uint32_t r;
    asm("cvt.rn.f16x2.f32 %0, %1, %2;" : "=r"(r) : "f"(hi), "f"(lo));
    return r;
}

__device__ __forceinline__ uint32_t h2ex2(uint32_t x) {
    uint32_t r;
    asm("ex2.approx.f16x2 %0, %1;" : "=r"(r) : "r"(x));
    return r;
}

__device__ __forceinline__ float ex2f(float x) {
    float y;
    asm("ex2.approx.ftz.f32 %0, %1;" : "=f"(y) : "f"(x));
    return y;
}

__device__ __forceinline__ void mma16(float* d, uint32_t a0, uint32_t a1,
                                      uint32_t a2, uint32_t a3,
                                      uint32_t b0, uint32_t b1) {
    asm volatile(
        "mma.sync.aligned.m16n8k16.row.col.f32.f16.f16.f32 "
        "{%0,%1,%2,%3}, {%4,%5,%6,%7}, {%8,%9}, {%0,%1,%2,%3};"
        : "+f"(d[0]), "+f"(d[1]), "+f"(d[2]), "+f"(d[3])
        : "r"(a0), "r"(a1), "r"(a2), "r"(a3), "r"(b0), "r"(b1));
}

__device__ __forceinline__ void ldsm4(uint32_t& r0, uint32_t& r1,
                                      uint32_t& r2, uint32_t& r3, uint32_t addr) {
    asm volatile("ldmatrix.sync.aligned.m8n8.x4.shared.b16 {%0,%1,%2,%3}, [%4];"
                 : "=r"(r0), "=r"(r1), "=r"(r2), "=r"(r3) : "r"(addr));
}

__device__ __forceinline__ void ldsm4t(uint32_t& r0, uint32_t& r1,
                                       uint32_t& r2, uint32_t& r3, uint32_t addr) {
    asm volatile("ldmatrix.sync.aligned.m8n8.x4.trans.shared.b16 {%0,%1,%2,%3}, [%4];"
                 : "=r"(r0), "=r"(r1), "=r"(r2), "=r"(r3) : "r"(addr));
}

__device__ __forceinline__ void cpa16(uint32_t dst, const void* src) {
    asm volatile("cp.async.cg.shared.global [%0], [%1], 16;"
                 :: "r"(dst), "l"(src));
}
#define CP_COMMIT() asm volatile("cp.async.commit_group;" ::: "memory")
#define CP_WAIT1()  asm volatile("cp.async.wait_group 1;" ::: "memory")

// ===========================================================================
// f32 -> f16 convert (vectorized, one-shot)
// ===========================================================================
__global__ void f2h(const float* __restrict__ s, __half* __restrict__ d, int n4) {
    int i = blockIdx.x * blockDim.x + threadIdx.x;
    if (i < n4) {
        float4 v = reinterpret_cast<const float4*>(s)[i];
        uint32_t* o = reinterpret_cast<uint32_t*>(d);
        o[2 * i]     = packh2(v.y, v.x);
        o[2 * i + 1] = packh2(v.w, v.z);
    }
}

// ===========================================================================
// fp16 GEMM, cp.async 3-stage pipeline:
// C[4096,1024] = A_h[4096,1024] @ W_h[1024,1024]^T + bias; out f16*scale or f32
// BM=BN=128, BK=32, 8 warps (4m x 2n), warp 32m x 64n.
// ===========================================================================
#define GPH 40                  // smem pitch (halves); 80B rows, 16B-aligned
#define STG_A (128 * GPH)       // halves per A stage
#define STG (2 * 128 * GPH)     // halves per stage (A + W)
#define G_SMEM (3 * STG * 2)    // 61440 bytes

__global__ __launch_bounds__(256, 2)
void gemm16(const __half* __restrict__ Ab, int astride_z,
            const __half* __restrict__ Wb, const float* __restrict__ bias,
            __half* o0, __half* o1, __half* o2, float* of32, float scale0)
{
    extern __shared__ __half smh[];
    const uint32_t sb = smem_u32(smh);

    const int z = blockIdx.z;
    const __half* A = Ab + (size_t)z * astride_z;
    const __half* Wz = Wb + (size_t)z * EMB * EMB;
    const float* bz = bias + z * EMB;
    __half* Ch = (z == 0) ? o0 : (z == 1) ? o1 : o2;
    const float scale = (z == 0) ? scale0 : 1.0f;

    const int tid = threadIdx.x;
    const int warp = tid >> 5;
    const int lane = tid & 31;
    const int gid = lane >> 2;
    const int tig = lane & 3;
    const int ri = lane & 7;
    const int mi = lane >> 3;
    const int wm = warp & 3;
    const int wn = warp >> 2;
    const int m0 = blockIdx.y * 128;
    const int n0 = blockIdx.x * 128;

    float acc[2][8][4];
#pragma unroll
    for (int mt = 0; mt < 2; ++mt)
#pragma unroll
        for (int nt = 0; nt < 8; ++nt)
#pragma unroll
            for (int r = 0; r < 4; ++r) acc[mt][nt][r] = 0.0f;

    // issue one k-tile (32 halves wide) into stage st: 1024 x 16B chunks
    auto issue = [&](int st, int kt) {
#pragma unroll
        for (int p = 0; p < 4; ++p) {
            int idx = p * 256 + tid;
            int isW = idx >> 9;            // 0: A, 1: W
            int i2 = idx & 511;
            int row = i2 >> 2;
            int c = i2 & 3;
            const __half* src = (isW ? Wz + (size_t)(n0 + row) * KDIM
                                     : A + (size_t)(m0 + row) * KDIM)
                                + kt * 32 + c * 8;
            uint32_t dst = sb + (uint32_t)(st * STG + isW * STG_A + row * GPH) * 2
                           + (uint32_t)c * 16;
            cpa16(dst, src);
        }
        CP_COMMIT();
    };

    issue(0, 0);
    issue(1, 1);

    for (int kt = 0; kt < 32; ++kt) {
        const int st = kt % 3;
        CP_WAIT1();
        __syncthreads();

        const uint32_t baseA = sb + (uint32_t)(st * STG) * 2;
        const uint32_t baseW = sb + (uint32_t)(st * STG + STG_A) * 2;
#pragma unroll
        for (int ks = 0; ks < 2; ++ks) {
            const int k0 = ks * 16;
            uint32_t a[2][4];
#pragma unroll
            for (int mt = 0; mt < 2; ++mt) {
                uint32_t addr = baseA + 2 * ((wm * 32 + mt * 16 + ri + (mi & 1) * 8) * GPH
                                             + k0 + (mi >> 1) * 8);
                ldsm4(a[mt][0], a[mt][1], a[mt][2], a[mt][3], addr);
            }
#pragma unroll
            for (int nt2 = 0; nt2 < 4; ++nt2) {
                uint32_t b0, b1, b2, b3;
                uint32_t addr = baseW + 2 * ((wn * 64 + nt2 * 16 + ri + (mi >> 1) * 8) * GPH
                                             + k0 + (mi & 1) * 8);
                ldsm4(b0, b1, b2, b3, addr);
#pragma unroll
                for (int mt = 0; mt < 2; ++mt) {
                    mma16(acc[mt][2 * nt2],     a[mt][0], a[mt][1], a[mt][2], a[mt][3], b0, b1);
                    mma16(acc[mt][2 * nt2 + 1], a[mt][0], a[mt][1], a[mt][2], a[mt][3], b2, b3);
                }
            }
        }
        __syncthreads();
        if (kt + 2 < 32) issue((kt + 2) % 3, kt + 2);
        else CP_COMMIT();   // keep group accounting for CP_WAIT1
    }

    // epilogue
#pragma unroll
    for (int mt = 0; mt < 2; ++mt) {
        int r = m0 + wm * 32 + mt * 16 + gid;
#pragma unroll
        for (int nt = 0; nt < 8; ++nt) {
            int c = n0 + wn * 64 + nt * 8 + 2 * tig;
            float bx = bz[c], by = bz[c + 1];
            if (of32) {
                float2 p0 = make_float2(acc[mt][nt][0] + bx, acc[mt][nt][1] + by);
                float2 p1 = make_float2(acc[mt][nt][2] + bx, acc[mt][nt][3] + by);
                *reinterpret_cast<float2*>(of32 + (size_t)r * EMB + c) = p0;
                *reinterpret_cast<float2*>(of32 + (size_t)(r + 8) * EMB + c) = p1;
            } else {
                uint32_t w0 = packh2((acc[mt][nt][1] + by) * scale,
                                     (acc[mt][nt][0] + bx) * scale);
                uint32_t w1 = packh2((acc[mt][nt][3] + by) * scale,
                                     (acc[mt][nt][2] + bx) * scale);
                *reinterpret_cast<uint32_t*>(Ch + (size_t)r * EMB + c) = w0;
                *reinterpret_cast<uint32_t*>(Ch + (size_t)(r + 8) * EMB + c) = w1;
            }
        }
    }
}

// ===========================================================================
// Flash attention: f16 in/out, cp.async double-buffered K/V, register-resident P
// CTA 128q x 128k, 8 warps; warp = 16 query rows. Row sums via ones-column mma.
// smem halves: Q[128][72], K[2][128][72], V[2][128][72]  (92160 B)
// ===========================================================================
#define FPH 72
#define TILE_H (128 * FPH)
#define F_SMEM_BYTES (5 * TILE_H * 2)   // 92160

__global__ __launch_bounds__(256, 2)
void flash_attn(const __half* __restrict__ gq, const __half* __restrict__ gk,
                const __half* __restrict__ gv, __half* __restrict__ ctx)
{
    extern __shared__ __half smh[];
    const uint32_t sb = smem_u32(smh);

    const int tid = threadIdx.x;
    const int warp = tid >> 5;
    const int lane = tid & 31;
    const int gid = lane >> 2;
    const int tig = lane & 3;
    const int ri = lane & 7;
    const int mi = lane >> 3;

    const int q0 = blockIdx.x * 128;
    const int bh = blockIdx.y;
    const int b = bh & (BB - 1);
    const int h = bh >> 1;
    const size_t hoff = (size_t)h * HDIM;
    const int rowQ = warp * 16;

    // K stage st at halves offset TILE_H*(1+st); V at TILE_H*(3+st)
    auto issueKV = [&](int st, int s0) {
#pragma unroll
        for (int p = 0; p < 8; ++p) {
            int idx = p * 256 + tid;           // 0..2047
            int isV = idx >> 10;
            int i2 = idx & 1023;
            int j = i2 >> 3;
            int c = i2 & 7;
            const __half* src = (isV ? gv : gk)
                + ((size_t)(s0 + j) * BB + b) * EMB + hoff + c * 8;
            uint32_t dst = sb + (uint32_t)(TILE_H * (1 + 2 * isV + st) + j * FPH) * 2
                           + (uint32_t)c * 16;
            cpa16(dst, src);
        }
        CP_COMMIT();
    };

    // group 0: Q + KV tile 0
#pragma unroll
    for (int p = 0; p < 4; ++p) {
        int idx = p * 256 + tid;               // 0..1023
        int i = idx >> 3;
        int c = idx & 7;
        const __half* src = gq + ((size_t)(q0 + i) * BB + b) * EMB + hoff + c * 8;
        cpa16(sb + (uint32_t)(i * FPH) * 2 + (uint32_t)c * 16, src);
    }
#pragma unroll
    for (int p = 0; p < 8; ++p) {
        int idx = p * 256 + tid;
        int isV = idx >> 10;
        int i2 = idx & 1023;
        int j = i2 >> 3;
        int c = i2 & 7;
        const __half* src = (isV ? gv : gk) + ((size_t)j * BB + b) * EMB + hoff + c * 8;
        cpa16(sb + (uint32_t)(TILE_H * (1 + 2 * isV) + j * FPH) * 2 + (uint32_t)c * 16, src);
    }
    CP_COMMIT();
    issueKV(1, 128);   // group 1: KV tile 1

    float m0r = -1e30f, m1r = -1e30f, l0 = 0.0f, l1 = 0.0f;
    float Of[8][4];
#pragma unroll
    for (int nt = 0; nt < 8; ++nt)
#pragma unroll
        for (int r = 0; r < 4; ++r) Of[nt][r] = 0.0f;

    const uint32_t ones = (gid == 0) ? 0x3C003C00u : 0u;  // fp16 (1,1) at n==0

    for (int t = 0; t < 16; ++t) {
        const int st = t & 1;
        const uint32_t SKH = TILE_H * (1 + st);
        const uint32_t SVH = TILE_H * (3 + st);
        CP_WAIT1();
        __syncthreads();

        // ---- S = Q @ K^T (Q pre-scaled by log2e/8): warp 16 x 128
        float sfr[16][4];
#pragma unroll
        for (int nt = 0; nt < 16; ++nt)
#pragma unroll
            for (int r = 0; r < 4; ++r) sfr[nt][r] = 0.0f;

#pragma unroll
        for (int ks = 0; ks < 4; ++ks) {
            const int k0 = ks * 16;
            uint32_t a0, a1, a2, a3;
            ldsm4(a0, a1, a2, a3,
                  sb + 2 * ((rowQ + ri + (mi & 1) * 8) * FPH + k0 + (mi >> 1) * 8));
#pragma unroll
            for (int nt2 = 0; nt2 < 8; ++nt2) {
                uint32_t b0, b1, b2, b3;
                ldsm4(b0, b1, b2, b3,
                      sb + 2 * (SKH + (nt2 * 16 + ri + (mi >> 1) * 8) * FPH + k0 + (mi & 1) * 8));
                mma16(sfr[2 * nt2],     a0, a1, a2, a3, b0, b1);
                mma16(sfr[2 * nt2 + 1], a0, a1, a2, a3, b2, b3);
            }
        }

        // ---- online softmax (base 2)
        float mx0 = sfr[0][0], mx1 = sfr[0][2];
#pragma unroll
        for (int nt = 0; nt < 16; ++nt) {
            mx0 = fmaxf(mx0, fmaxf(sfr[nt][0], sfr[nt][1]));
            mx1 = fmaxf(mx1, fmaxf(sfr[nt][2], sfr[nt][3]));
        }
#pragma unroll
        for (int off = 1; off <= 2; off <<= 1) {
            mx0 = fmaxf(mx0, __shfl_xor_sync(0xffffffffu, mx0, off));
            mx1 = fmaxf(mx1, __shfl_xor_sync(0xffffffffu, mx1, off));
        }
        float mn0 = fmaxf(m0r, mx0), mn1 = fmaxf(m1r, mx1);
        float c0 = ex2f(m0r - mn0), c1 = ex2f(m1r - mn1);
        m0r = mn0; m1r = mn1;

        // P = 2^(s-mn), packed f16x2 — these ARE the PV A-fragments (row gid / gid+8)
        uint32_t pk0[16], pk1[16];
#pragma unroll
        for (int nt = 0; nt < 16; ++nt) {
            pk0[nt] = h2ex2(packh2(sfr[nt][1] - mn0, sfr[nt][0] - mn0));
            pk1[nt] = h2ex2(packh2(sfr[nt][3] - mn1, sfr[nt][2] - mn1));
        }
#pragma unroll
        for (int nt = 0; nt < 8; ++nt) {
            Of[nt][0] *= c0; Of[nt][1] *= c0;
            Of[nt][2] *= c1; Of[nt][3] *= c1;
        }
        float lacc[4] = {0.0f, 0.0f, 0.0f, 0.0f};

        // ---- O += P @ V (+ row sums via ones column): k = 128 (8 steps)
#pragma unroll
        for (int ks = 0; ks < 8; ++ks) {
            uint32_t a0 = pk0[2 * ks], a1 = pk1[2 * ks];
            uint32_t a2 = pk0[2 * ks + 1], a3 = pk1[2 * ks + 1];
#pragma unroll
            for (int dt2 = 0; dt2 < 4; ++dt2) {
                uint32_t b0, b1, b2, b3;
                ldsm4t(b0, b1, b2, b3,
                       sb + 2 * (SVH + (ks * 16 + ri + (mi & 1) * 8) * FPH
                                 + dt2 * 16 + (mi >> 1) * 8));
                mma16(Of[2 * dt2],     a0, a1, a2, a3, b0, b1);
                mma16(Of[2 * dt2 + 1], a0, a1, a2, a3, b2, b3);
            }
            mma16(lacc, a0, a1, a2, a3, ones, ones);
        }
        l0 = l0 * c0 + lacc[0];
        l1 = l1 * c1 + lacc[2];

        __syncthreads();
        if (t + 2 < 16) issueKV(st, (t + 2) * 128);
        else CP_COMMIT();
    }

    // broadcast row sums from tig==0 lanes, normalize, store f16 ctx
    const int src = lane & ~3;
    float l0b = __shfl_sync(0xffffffffu, l0, src);
    float l1b = __shfl_sync(0xffffffffu, l1, src);
    float i0 = 1.0f / l0b, i1 = 1.0f / l1b;
    int r = q0 + rowQ + gid;
#pragma unroll
    for (int nt = 0; nt < 8; ++nt) {
        int d = nt * 8 + 2 * tig;
        uint32_t w0 = packh2(Of[nt][1] * i0, Of[nt][0] * i0);
        uint32_t w1 = packh2(Of[nt][3] * i1, Of[nt][2] * i1);
        *reinterpret_cast<uint32_t*>(ctx + ((size_t)r * BB + b) * EMB + hoff + d) = w0;
        *reinterpret_cast<uint32_t*>(ctx + ((size_t)(r + 8) * BB + b) * EMB + hoff + d) = w1;
    }
}

// ---------------------------------------------------------------------------
extern "C" void kernel_launch(void* const* d_in, const int* in_sizes, int n_in,
                              void* d_out, int out_size)
{
    const float* query = (const float*)d_in[0];
    const float* key   = (const float*)d_in[1];
    const float* value = (const float*)d_in[2];
    const float* w_in  = (const float*)d_in[3];
    const float* b_in  = (const float*)d_in[4];
    const float* w_out = (const float*)d_in[5];
    const float* b_out = (const float*)d_in[6];
    float* out = (float*)d_out;

    __half *ah, *wh, *qh, *kh, *vh, *ch;
    cudaGetSymbolAddress((void**)&ah, g_ah);
    cudaGetSymbolAddress((void**)&wh, g_wh);
    cudaGetSymbolAddress((void**)&qh, g_qh);
    cudaGetSymbolAddress((void**)&kh, g_kh);
    cudaGetSymbolAddress((void**)&vh, g_vh);
    cudaGetSymbolAddress((void**)&ch, g_ch);

    const float QSC = 0.180336880f;  // log2(e) / 8

    // one-shot f32 -> f16 conversion of inputs and weights
    const int NIN = MROWS * KDIM;             // 4M elements per input
    f2h<<<NIN / 4 / 256, 256>>>(query, ah, NIN / 4);
    f2h<<<NIN / 4 / 256, 256>>>(key,   ah + NIN, NIN / 4);
    f2h<<<NIN / 4 / 256, 256>>>(value, ah + 2 * NIN, NIN / 4);
    f2h<<<3 * EMB * EMB / 4 / 256, 256>>>(w_in, wh, 3 * EMB * EMB / 4);
    f2h<<<EMB * EMB / 4 / 256, 256>>>(w_out, wh + 3 * EMB * EMB, EMB * EMB / 4);

    cudaFuncSetAttribute(gemm16, cudaFuncAttributeMaxDynamicSharedMemorySize, G_SMEM);
    cudaFuncSetAttribute(flash_attn, cudaFuncAttributeMaxDynamicSharedMemorySize, F_SMEM_BYTES);

    // fused QKV projection (q pre-scaled by QSC)
    dim3 qkv_grid(EMB / 128, MROWS / 128, 3);
    gemm16<<<qkv_grid, 256, G_SMEM>>>(ah, NIN, wh, b_in, qh, kh, vh, nullptr, QSC);

    dim3 flash_grid(LQ / 128, BB * NHEAD);  // (16, 32)
    flash_attn<<<flash_grid, 256, F_SMEM_BYTES>>>(qh, kh, vh, ch);

    // out projection -> f32 d_out
    dim3 out_grid(EMB / 128, MROWS / 128, 1);
    gemm16<<<out_grid, 256, G_SMEM>>>(ch, 0, wh + 3 * EMB * EMB, b_out,
                                      nullptr, nullptr, nullptr, out, 1.0f);
}

// round 11
// speedup vs baseline: 7.0963x; 1.0613x over previous
#include <cuda_runtime.h>
#include <cuda_fp16.h>
#include <math.h>
#include <cstdint>

// Problem constants
#define EMB   1024
#define NHEAD 16
#define HDIM  64
#define LQ    2048
#define BB    2
#define SS    2048
#define MROWS (LQ * BB)   // 4096
#define KDIM  1024

// ---------------- device scratch (no allocation allowed) ----------------
__device__ __half g_ah[3 * MROWS * KDIM];   // converted query/key/value inputs
__device__ __half g_wh[4 * EMB * EMB];      // converted w_in (3M) + w_out (1M)
__device__ __half g_qh[MROWS * EMB];        // q projection (pre-scaled by log2e/8)
__device__ __half g_kh[MROWS * EMB];
__device__ __half g_vh[MROWS * EMB];
__device__ __half g_ch[MROWS * EMB];        // attention context (f16)

// ======================= helpers =======================
__device__ __forceinline__ uint32_t smem_u32(const void* p) {
    uint32_t a;
    asm("{ .reg .u64 t; cvta.to.shared.u64 t, %1; cvt.u32.u64 %0, t; }"
        : "=r"(a) : "l"(p));
    return a;
}

__device__ __forceinline__ uint32_t packh2(float hi, float lo) {
    uint32_t r;
    asm("cvt.rn.f16x2.f32 %0, %1, %2;" : "=r"(r) : "f"(hi), "f"(lo));
    return r;
}

__device__ __forceinline__ uint32_t h2ex2(uint32_t x) {
    uint32_t r;
    asm("ex2.approx.f16x2 %0, %1;" : "=r"(r) : "r"(x));
    return r;
}

__device__ __forceinline__ float ex2f(float x) {
    float y;
    asm("ex2.approx.ftz.f32 %0, %1;" : "=f"(y) : "f"(x));
    return y;
}

__device__ __forceinline__ void mma16(float* d, uint32_t a0, uint32_t a1,
                                      uint32_t a2, uint32_t a3,
                                      uint32_t b0, uint32_t b1) {
    asm volatile(
        "mma.sync.aligned.m16n8k16.row.col.f32.f16.f16.f32 "
        "{%0,%1,%2,%3}, {%4,%5,%6,%7}, {%8,%9}, {%0,%1,%2,%3};"
        : "+f"(d[0]), "+f"(d[1]), "+f"(d[2]), "+f"(d[3])
        : "r"(a0), "r"(a1), "r"(a2), "r"(a3), "r"(b0), "r"(b1));
}

__device__ __forceinline__ void ldsm4(uint32_t& r0, uint32_t& r1,
                                      uint32_t& r2, uint32_t& r3, uint32_t addr) {
    asm volatile("ldmatrix.sync.aligned.m8n8.x4.shared.b16 {%0,%1,%2,%3}, [%4];"
                 : "=r"(r0), "=r"(r1), "=r"(r2), "=r"(r3) : "r"(addr));
}

__device__ __forceinline__ void ldsm4t(uint32_t& r0, uint32_t& r1,
                                       uint32_t& r2, uint32_t& r3, uint32_t addr) {
    asm volatile("ldmatrix.sync.aligned.m8n8.x4.trans.shared.b16 {%0,%1,%2,%3}, [%4];"
                 : "=r"(r0), "=r"(r1), "=r"(r2), "=r"(r3) : "r"(addr));
}

__device__ __forceinline__ void cpa16(uint32_t dst, const void* src) {
    asm volatile("cp.async.cg.shared.global [%0], [%1], 16;"
                 :: "r"(dst), "l"(src));
}
#define CP_COMMIT() asm volatile("cp.async.commit_group;" ::: "memory")
#define CP_WAIT1()  asm volatile("cp.async.wait_group 1;" ::: "memory")

// ===========================================================================
// Fused f32 -> f16 conversion: query/key/value -> g_ah, w_in/w_out -> g_wh.
// One launch, indexed in float4 units (4,194,304 total).
// ===========================================================================
#define N4_IN   1048576   // float4s per input tensor (4M elts)
#define N4_WIN  786432    // float4s in w_in
#define N4_WOUT 262144    // float4s in w_out
#define N4_TOT  (3 * N4_IN + N4_WIN + N4_WOUT)

__global__ void f2h_all(const float* __restrict__ q, const float* __restrict__ k,
                        const float* __restrict__ v, const float* __restrict__ wi,
                        const float* __restrict__ wo,
                        __half* __restrict__ ah, __half* __restrict__ wh)
{
    int i = blockIdx.x * blockDim.x + threadIdx.x;
    const float* src;
    uint32_t* dst;
    int li;
    if (i < 3 * N4_IN) {
        int s = i >> 20;                  // /N4_IN
        li = i & (N4_IN - 1);
        src = (s == 0) ? q : (s == 1) ? k : v;
        dst = reinterpret_cast<uint32_t*>(ah) + 2 * (size_t)i;
    } else if (i < 3 * N4_IN + N4_WIN) {
        li = i - 3 * N4_IN;
        src = wi;
        dst = reinterpret_cast<uint32_t*>(wh) + 2 * (size_t)li;
    } else {
        li = i - 3 * N4_IN - N4_WIN;
        src = wo;
        dst = reinterpret_cast<uint32_t*>(wh) + 2 * (size_t)(N4_WIN + li);
    }
    float4 x = reinterpret_cast<const float4*>(src)[li];
    dst[0] = packh2(x.y, x.x);
    dst[1] = packh2(x.w, x.z);
}

// ===========================================================================
// fp16 GEMM, cp.async 3-stage pipeline, ONE sync per k-tile:
// C[4096,1024] = A_h[4096,1024] @ W_h[1024,1024]^T + bias; out f16*scale or f32
// BM=BN=128, BK=32, 8 warps (4m x 2n), warp 32m x 64n.
// ===========================================================================
#define GPH 40                  // smem pitch (halves); 80B rows, 16B-aligned
#define STG_A (128 * GPH)       // halves per A stage
#define STG (2 * 128 * GPH)     // halves per stage (A + W)
#define G_SMEM (3 * STG * 2)    // 61440 bytes

__global__ __launch_bounds__(256, 2)
void gemm16(const __half* __restrict__ Ab, int astride_z,
            const __half* __restrict__ Wb, const float* __restrict__ bias,
            __half* o0, __half* o1, __half* o2, float* of32, float scale0)
{
    extern __shared__ __half smh[];
    const uint32_t sb = smem_u32(smh);

    const int z = blockIdx.z;
    const __half* A = Ab + (size_t)z * astride_z;
    const __half* Wz = Wb + (size_t)z * EMB * EMB;
    const float* bz = bias + z * EMB;
    __half* Ch = (z == 0) ? o0 : (z == 1) ? o1 : o2;
    const float scale = (z == 0) ? scale0 : 1.0f;

    const int tid = threadIdx.x;
    const int warp = tid >> 5;
    const int lane = tid & 31;
    const int gid = lane >> 2;
    const int tig = lane & 3;
    const int ri = lane & 7;
    const int mi = lane >> 3;
    const int wm = warp & 3;
    const int wn = warp >> 2;
    const int m0 = blockIdx.y * 128;
    const int n0 = blockIdx.x * 128;

    float acc[2][8][4];
#pragma unroll
    for (int mt = 0; mt < 2; ++mt)
#pragma unroll
        for (int nt = 0; nt < 8; ++nt)
#pragma unroll
            for (int r = 0; r < 4; ++r) acc[mt][nt][r] = 0.0f;

    auto issue = [&](int st, int kt) {
#pragma unroll
        for (int p = 0; p < 4; ++p) {
            int idx = p * 256 + tid;
            int isW = idx >> 9;
            int i2 = idx & 511;
            int row = i2 >> 2;
            int c = i2 & 3;
            const __half* src = (isW ? Wz + (size_t)(n0 + row) * KDIM
                                     : A + (size_t)(m0 + row) * KDIM)
                                + kt * 32 + c * 8;
            uint32_t dst = sb + (uint32_t)(st * STG + isW * STG_A + row * GPH) * 2
                           + (uint32_t)c * 16;
            cpa16(dst, src);
        }
        CP_COMMIT();
    };

    issue(0, 0);
    issue(1, 1);

    for (int kt = 0; kt < 32; ++kt) {
        const int st = kt % 3;
        CP_WAIT1();
        __syncthreads();
        // issue into stage (kt-1)%3, whose readers finished before the sync above
        if (kt + 2 < 32) issue((kt + 2) % 3, kt + 2);
        else CP_COMMIT();

        const uint32_t baseA = sb + (uint32_t)(st * STG) * 2;
        const uint32_t baseW = sb + (uint32_t)(st * STG + STG_A) * 2;
#pragma unroll
        for (int ks = 0; ks < 2; ++ks) {
            const int k0 = ks * 16;
            uint32_t a[2][4];
#pragma unroll
            for (int mt = 0; mt < 2; ++mt) {
                uint32_t addr = baseA + 2 * ((wm * 32 + mt * 16 + ri + (mi & 1) * 8) * GPH
                                             + k0 + (mi >> 1) * 8);
                ldsm4(a[mt][0], a[mt][1], a[mt][2], a[mt][3], addr);
            }
#pragma unroll
            for (int nt2 = 0; nt2 < 4; ++nt2) {
                uint32_t b0, b1, b2, b3;
                uint32_t addr = baseW + 2 * ((wn * 64 + nt2 * 16 + ri + (mi >> 1) * 8) * GPH
                                             + k0 + (mi & 1) * 8);
                ldsm4(b0, b1, b2, b3, addr);
#pragma unroll
                for (int mt = 0; mt < 2; ++mt) {
                    mma16(acc[mt][2 * nt2],     a[mt][0], a[mt][1], a[mt][2], a[mt][3], b0, b1);
                    mma16(acc[mt][2 * nt2 + 1], a[mt][0], a[mt][1], a[mt][2], a[mt][3], b2, b3);
                }
            }
        }
    }

    // epilogue
#pragma unroll
    for (int mt = 0; mt < 2; ++mt) {
        int r = m0 + wm * 32 + mt * 16 + gid;
#pragma unroll
        for (int nt = 0; nt < 8; ++nt) {
            int c = n0 + wn * 64 + nt * 8 + 2 * tig;
            float bx = bz[c], by = bz[c + 1];
            if (of32) {
                float2 p0 = make_float2(acc[mt][nt][0] + bx, acc[mt][nt][1] + by);
                float2 p1 = make_float2(acc[mt][nt][2] + bx, acc[mt][nt][3] + by);
                *reinterpret_cast<float2*>(of32 + (size_t)r * EMB + c) = p0;
                *reinterpret_cast<float2*>(of32 + (size_t)(r + 8) * EMB + c) = p1;
            } else {
                uint32_t w0 = packh2((acc[mt][nt][1] + by) * scale,
                                     (acc[mt][nt][0] + bx) * scale);
                uint32_t w1 = packh2((acc[mt][nt][3] + by) * scale,
                                     (acc[mt][nt][2] + bx) * scale);
                *reinterpret_cast<uint32_t*>(Ch + (size_t)r * EMB + c) = w0;
                *reinterpret_cast<uint32_t*>(Ch + (size_t)(r + 8) * EMB + c) = w1;
            }
        }
    }
}

// ===========================================================================
// Flash attention: f16 in/out, 3-stage cp.async K/V with SW128-style swizzle
// (128B rows, chunk ^= row&7, no padding), ONE sync per KV tile.
// CTA 128q x 128k, 8 warps; warp = 16 query rows; register-resident P.
// smem tiles (128x64 halves = 16KB): Q | K0 K1 K2 | V0 V1 V2  = 114688 B
// ===========================================================================
#define FT 8192                       // halves per tile
#define F_SMEM_BYTES (7 * FT * 2)     // 114688

__device__ __forceinline__ uint32_t sw_off(int tile, int row, int chunk) {
    return (uint32_t)(tile * FT + row * 64 + (((chunk) ^ (row & 7)) << 3));
}

__global__ __launch_bounds__(256, 2)
void flash_attn(const __half* __restrict__ gq, const __half* __restrict__ gk,
                const __half* __restrict__ gv, __half* __restrict__ ctx)
{
    extern __shared__ __half smh[];
    const uint32_t sb = smem_u32(smh);

    const int tid = threadIdx.x;
    const int warp = tid >> 5;
    const int lane = tid & 31;
    const int gid = lane >> 2;
    const int tig = lane & 3;
    const int ri = lane & 7;
    const int mi = lane >> 3;

    const int q0 = blockIdx.x * 128;
    const int bh = blockIdx.y;
    const int b = bh & (BB - 1);
    const int h = bh >> 1;
    const size_t hoff = (size_t)h * HDIM;
    const int rowQ = warp * 16;

    auto issueKV = [&](int st, int s0) {
#pragma unroll
        for (int p = 0; p < 8; ++p) {
            int idx = p * 256 + tid;           // 0..2047
            int isV = idx >> 10;
            int i2 = idx & 1023;
            int j = i2 >> 3;
            int c = i2 & 7;
            const __half* src = (isV ? gv : gk)
                + ((size_t)(s0 + j) * BB + b) * EMB + hoff + c * 8;
            cpa16(sb + 2 * sw_off((isV ? 4 : 1) + st, j, c), src);
        }
        CP_COMMIT();
    };

    // group 0: Q + KV tile 0
#pragma unroll
    for (int p = 0; p < 4; ++p) {
        int idx = p * 256 + tid;               // 0..1023
        int i = idx >> 3;
        int c = idx & 7;
        const __half* src = gq + ((size_t)(q0 + i) * BB + b) * EMB + hoff + c * 8;
        cpa16(sb + 2 * sw_off(0, i, c), src);
    }
#pragma unroll
    for (int p = 0; p < 8; ++p) {
        int idx = p * 256 + tid;
        int isV = idx >> 10;
        int i2 = idx & 1023;
        int j = i2 >> 3;
        int c = i2 & 7;
        const __half* src = (isV ? gv : gk) + ((size_t)j * BB + b) * EMB + hoff + c * 8;
        cpa16(sb + 2 * sw_off((isV ? 4 : 1), j, c), src);
    }
    CP_COMMIT();
    issueKV(1, 128);   // group 1: KV tile 1 -> stage 1

    float m0r = -1e30f, m1r = -1e30f, l0 = 0.0f, l1 = 0.0f;
    float Of[8][4];
#pragma unroll
    for (int nt = 0; nt < 8; ++nt)
#pragma unroll
        for (int r = 0; r < 4; ++r) Of[nt][r] = 0.0f;

    const uint32_t ones = (gid == 0) ? 0x3C003C00u : 0u;  // fp16 (1,1) at n==0

    for (int t = 0; t < 16; ++t) {
        const int st = t % 3;
        CP_WAIT1();
        __syncthreads();
        // prefetch into stage (t-1)%3: its readers finished before the sync above
        if (t + 2 < 16) issueKV((t + 2) % 3, (t + 2) * 128);
        else CP_COMMIT();

        // ---- S = Q @ K^T (Q pre-scaled by log2e/8): warp 16 x 128
        float sfr[16][4];
#pragma unroll
        for (int nt = 0; nt < 16; ++nt)
#pragma unroll
            for (int r = 0; r < 4; ++r) sfr[nt][r] = 0.0f;

#pragma unroll
        for (int ks = 0; ks < 4; ++ks) {
            uint32_t a0, a1, a2, a3;
            ldsm4(a0, a1, a2, a3,
                  sb + 2 * sw_off(0, rowQ + ri + (mi & 1) * 8, ks * 2 + (mi >> 1)));
#pragma unroll
            for (int nt2 = 0; nt2 < 8; ++nt2) {
                uint32_t b0, b1, b2, b3;
                ldsm4(b0, b1, b2, b3,
                      sb + 2 * sw_off(1 + st, nt2 * 16 + ri + (mi >> 1) * 8,
                                      ks * 2 + (mi & 1)));
                mma16(sfr[2 * nt2],     a0, a1, a2, a3, b0, b1);
                mma16(sfr[2 * nt2 + 1], a0, a1, a2, a3, b2, b3);
            }
        }

        // ---- online softmax (base 2)
        float mx0 = sfr[0][0], mx1 = sfr[0][2];
#pragma unroll
        for (int nt = 0; nt < 16; ++nt) {
            mx0 = fmaxf(mx0, fmaxf(sfr[nt][0], sfr[nt][1]));
            mx1 = fmaxf(mx1, fmaxf(sfr[nt][2], sfr[nt][3]));
        }
#pragma unroll
        for (int off = 1; off <= 2; off <<= 1) {
            mx0 = fmaxf(mx0, __shfl_xor_sync(0xffffffffu, mx0, off));
            mx1 = fmaxf(mx1, __shfl_xor_sync(0xffffffffu, mx1, off));
        }
        float mn0 = fmaxf(m0r, mx0), mn1 = fmaxf(m1r, mx1);
        float c0 = ex2f(m0r - mn0), c1 = ex2f(m1r - mn1);
        m0r = mn0; m1r = mn1;

        // P = 2^(s-mn), packed f16x2 — these ARE the PV A-fragments
        uint32_t pk0[16], pk1[16];
#pragma unroll
        for (int nt = 0; nt < 16; ++nt) {
            pk0[nt] = h2ex2(packh2(sfr[nt][1] - mn0, sfr[nt][0] - mn0));
            pk1[nt] = h2ex2(packh2(sfr[nt][3] - mn1, sfr[nt][2] - mn1));
        }
#pragma unroll
        for (int nt = 0; nt < 8; ++nt) {
            Of[nt][0] *= c0; Of[nt][1] *= c0;
            Of[nt][2] *= c1; Of[nt][3] *= c1;
        }
        float lacc[4] = {0.0f, 0.0f, 0.0f, 0.0f};

        // ---- O += P @ V (+ row sums via ones column): k = 128 (8 steps)
#pragma unroll
        for (int ks = 0; ks < 8; ++ks) {
            uint32_t a0 = pk0[2 * ks], a1 = pk1[2 * ks];
            uint32_t a2 = pk0[2 * ks + 1], a3 = pk1[2 * ks + 1];
#pragma unroll
            for (int dt2 = 0; dt2 < 4; ++dt2) {
                uint32_t b0, b1, b2, b3;
                ldsm4t(b0, b1, b2, b3,
                       sb + 2 * sw_off(4 + st, ks * 16 + ri + (mi & 1) * 8,
                                       dt2 * 2 + (mi >> 1)));
                mma16(Of[2 * dt2],     a0, a1, a2, a3, b0, b1);
                mma16(Of[2 * dt2 + 1], a0, a1, a2, a3, b2, b3);
            }
            mma16(lacc, a0, a1, a2, a3, ones, ones);
        }
        l0 = l0 * c0 + lacc[0];
        l1 = l1 * c1 + lacc[2];
    }

    // broadcast row sums from tig==0 lanes, normalize, store f16 ctx
    const int src = lane & ~3;
    float l0b = __shfl_sync(0xffffffffu, l0, src);
    float l1b = __shfl_sync(0xffffffffu, l1, src);
    float i0 = 1.0f / l0b, i1 = 1.0f / l1b;
    int r = q0 + rowQ + gid;
#pragma unroll
    for (int nt = 0; nt < 8; ++nt) {
        int d = nt * 8 + 2 * tig;
        uint32_t w0 = packh2(Of[nt][1] * i0, Of[nt][0] * i0);
        uint32_t w1 = packh2(Of[nt][3] * i1, Of[nt][2] * i1);
        *reinterpret_cast<uint32_t*>(ctx + ((size_t)r * BB + b) * EMB + hoff + d) = w0;
        *reinterpret_cast<uint32_t*>(ctx + ((size_t)(r + 8) * BB + b) * EMB + hoff + d) = w1;
    }
}

// ---------------------------------------------------------------------------
extern "C" void kernel_launch(void* const* d_in, const int* in_sizes, int n_in,
                              void* d_out, int out_size)
{
    const float* query = (const float*)d_in[0];
    const float* key   = (const float*)d_in[1];
    const float* value = (const float*)d_in[2];
    const float* w_in  = (const float*)d_in[3];
    const float* b_in  = (const float*)d_in[4];
    const float* w_out = (const float*)d_in[5];
    const float* b_out = (const float*)d_in[6];
    float* out = (float*)d_out;

    __half *ah, *wh, *qh, *kh, *vh, *ch;
    cudaGetSymbolAddress((void**)&ah, g_ah);
    cudaGetSymbolAddress((void**)&wh, g_wh);
    cudaGetSymbolAddress((void**)&qh, g_qh);
    cudaGetSymbolAddress((void**)&kh, g_kh);
    cudaGetSymbolAddress((void**)&vh, g_vh);
    cudaGetSymbolAddress((void**)&ch, g_ch);

    const float QSC = 0.180336880f;  // log2(e) / 8

    // one fused f32 -> f16 conversion launch
    f2h_all<<<N4_TOT / 256, 256>>>(query, key, value, w_in, w_out, ah, wh);

    cudaFuncSetAttribute(gemm16, cudaFuncAttributeMaxDynamicSharedMemorySize, G_SMEM);
    cudaFuncSetAttribute(flash_attn, cudaFuncAttributeMaxDynamicSharedMemorySize, F_SMEM_BYTES);

    // fused QKV projection (q pre-scaled by QSC)
    dim3 qkv_grid(EMB / 128, MROWS / 128, 3);
    gemm16<<<qkv_grid, 256, G_SMEM>>>(ah, MROWS * KDIM, wh, b_in, qh, kh, vh, nullptr, QSC);

    dim3 flash_grid(LQ / 128, BB * NHEAD);  // (16, 32)
    flash_attn<<<flash_grid, 256, F_SMEM_BYTES>>>(qh, kh, vh, ch);

    // out projection -> f32 d_out
    dim3 out_grid(EMB / 128, MROWS / 128, 1);
    gemm16<<<out_grid, 256, G_SMEM>>>(ch, 0, wh + 3 * EMB * EMB, b_out,
                                      nullptr, nullptr, nullptr, out, 1.0f);
}